// round 14
// baseline (speedup 1.0000x reference)
#include <cuda_runtime.h>
#include <cuda_bf16.h>
#include <cstdint>

// ShiftLayer: out[b,t,c] = in[b, t+off[c], c], off[c] = {0,-1,+1} for c%3 = {0,1,2},
// zero padding at sequence ends. B=8, L=8192, C=384, fp32.
//
// Paired-row 256-bit kernel (best measured config, R12) with two micro tweaks:
//   1. __launch_bounds__(256,6): the kernel fits in 40-42 regs, so allow 6
//      blocks/SM (48 warps resident) instead of declaring a 4-block ceiling.
//   2. ld.global.nc.v8.b32: read-only non-coherent loads (input and output
//      never alias) - texture-path streaming for the 2x-amplified read stream.
// One thread produces TWO consecutive output rows (t, t+1) at one 8-channel
// slot: 4 independent LDG.256 (rows t-1..t+2), two routed STG.256 with
// L2::evict_first (write-once output must not churn L2-resident input).

#define B_DIM 8
#define L_DIM 8192
#define C_DIM 384
#define SLOTS (C_DIM / 8)               // 48 float8 slots per row
#define THREADS 256

__device__ __forceinline__ void ld8(uint32_t* d, const float* p) {
    asm volatile("ld.global.nc.v8.b32 {%0,%1,%2,%3,%4,%5,%6,%7}, [%8];"
                 : "=r"(d[0]), "=r"(d[1]), "=r"(d[2]), "=r"(d[3]),
                   "=r"(d[4]), "=r"(d[5]), "=r"(d[6]), "=r"(d[7])
                 : "l"(p));
}
__device__ __forceinline__ void st8(float* p, const uint32_t* v) {
    asm volatile("st.global.L2::evict_first.v8.b32 [%0], {%1,%2,%3,%4,%5,%6,%7,%8};"
                 :: "l"(p),
                    "r"(v[0]), "r"(v[1]), "r"(v[2]), "r"(v[3]),
                    "r"(v[4]), "r"(v[5]), "r"(v[6]), "r"(v[7])
                 : "memory");
}

// Component j has channel residue (m + j) % 3; residue 0 -> C, 1 -> P, 2 -> N.
__device__ __forceinline__ void route8(uint32_t* o, const uint32_t* P,
                                       const uint32_t* C, const uint32_t* N,
                                       bool is1, bool is2) {
    #pragma unroll
    for (int j = 0; j < 8; ++j) {
        const int jc = j % 3;
        if (jc == 0)      o[j] = is1 ? P[j] : (is2 ? N[j] : C[j]);
        else if (jc == 1) o[j] = is1 ? N[j] : (is2 ? C[j] : P[j]);
        else              o[j] = is1 ? C[j] : (is2 ? P[j] : N[j]);
    }
}

__global__ __launch_bounds__(THREADS, 6)
void ShiftLayer_66932770341347_kernel(const float* __restrict__ in,
                                      float* __restrict__ out) {
    const int id = blockIdx.x * THREADS + threadIdx.x;   // (row-pair, slot) index

    const int pair = id / SLOTS;                 // b*(L/2) + t/2
    const int s    = id - pair * SLOTS;          // slot 0..47
    const int t    = (pair & (L_DIM / 2 - 1)) * 2;   // even row in [0, L)

    // Base channel residue: (8*s) % 3 == (2*s) % 3 (same for both rows)
    const int m = (2 * s) % 3;
    const bool is1 = (m == 1), is2 = (m == 2);

    // Flat element offset of (row t, slot s) for this pair's batch.
    const size_t base = ((size_t)(pair / (L_DIM / 2)) * L_DIM + t) * C_DIM + 8 * s;
    const float* p = in + base;

    uint32_t A[8], Bv[8], Cv[8], D[8];           // rows t-1, t, t+1, t+2
    ld8(Bv, p);
    ld8(Cv, p + C_DIM);
    if (t > 0) {
        ld8(A, p - C_DIM);
    } else {
        #pragma unroll
        for (int j = 0; j < 8; ++j) A[j] = 0u;
    }
    if (t + 2 < L_DIM) {
        ld8(D, p + 2 * C_DIM);
    } else {
        #pragma unroll
        for (int j = 0; j < 8; ++j) D[j] = 0u;
    }

    uint32_t o0[8], o1[8];
    route8(o0, A,  Bv, Cv, is1, is2);            // output row t
    route8(o1, Bv, Cv, D,  is1, is2);            // output row t+1

    float* q = out + base;
    st8(q,         o0);
    st8(q + C_DIM, o1);
}

extern "C" void kernel_launch(void* const* d_in, const int* in_sizes, int n_in,
                              void* d_out, int out_size) {
    const float* mem = (const float*)d_in[0];
    float* out = (float*)d_out;
    (void)in_sizes; (void)n_in; (void)out_size;

    const int total = B_DIM * (L_DIM / 2) * SLOTS;    // 1,572,864 threads
    const int grid  = total / THREADS;                // 6144 blocks
    ShiftLayer_66932770341347_kernel<<<grid, THREADS>>>(mem, out);
}

// round 16
// speedup vs baseline: 1.0072x; 1.0072x over previous
#include <cuda_runtime.h>
#include <cuda_bf16.h>
#include <cstdint>

// ShiftLayer: out[b,t,c] = in[b, t+off[c], c], off[c] = {0,-1,+1} for c%3 = {0,1,2},
// zero padding at sequence ends. B=8, L=8192, C=384, fp32.
//
// Paired-row 256-bit kernel (champion config R12) with ONE change vs R12:
// __launch_bounds__(256,6) -- the kernel fits in ~40 regs, so allow 6
// blocks/SM (48 resident warps, ~75% occ) instead of the previous 4-block
// ceiling. Loads stay plain ld.global.v8.b32 (R14 showed .nc regresses).
//
// One thread produces TWO consecutive output rows (t, t+1) at one 8-channel
// slot: 4 independent LDG.256 (rows t-1..t+2, no loop-carried rotation for
// ptxas to serialize), two routed STG.256 with L2::evict_first (write-once
// output must not churn L2-resident input -- proven win in R7).

#define B_DIM 8
#define L_DIM 8192
#define C_DIM 384
#define SLOTS (C_DIM / 8)               // 48 float8 slots per row
#define THREADS 256

__device__ __forceinline__ void ld8(uint32_t* d, const float* p) {
    asm volatile("ld.global.v8.b32 {%0,%1,%2,%3,%4,%5,%6,%7}, [%8];"
                 : "=r"(d[0]), "=r"(d[1]), "=r"(d[2]), "=r"(d[3]),
                   "=r"(d[4]), "=r"(d[5]), "=r"(d[6]), "=r"(d[7])
                 : "l"(p));
}
__device__ __forceinline__ void st8(float* p, const uint32_t* v) {
    asm volatile("st.global.L2::evict_first.v8.b32 [%0], {%1,%2,%3,%4,%5,%6,%7,%8};"
                 :: "l"(p),
                    "r"(v[0]), "r"(v[1]), "r"(v[2]), "r"(v[3]),
                    "r"(v[4]), "r"(v[5]), "r"(v[6]), "r"(v[7])
                 : "memory");
}

// Component j has channel residue (m + j) % 3; residue 0 -> C, 1 -> P, 2 -> N.
__device__ __forceinline__ void route8(uint32_t* o, const uint32_t* P,
                                       const uint32_t* C, const uint32_t* N,
                                       bool is1, bool is2) {
    #pragma unroll
    for (int j = 0; j < 8; ++j) {
        const int jc = j % 3;
        if (jc == 0)      o[j] = is1 ? P[j] : (is2 ? N[j] : C[j]);
        else if (jc == 1) o[j] = is1 ? N[j] : (is2 ? C[j] : P[j]);
        else              o[j] = is1 ? C[j] : (is2 ? P[j] : N[j]);
    }
}

__global__ __launch_bounds__(THREADS, 6)
void ShiftLayer_66932770341347_kernel(const float* __restrict__ in,
                                      float* __restrict__ out) {
    const int id = blockIdx.x * THREADS + threadIdx.x;   // (row-pair, slot) index

    const int pair = id / SLOTS;                 // b*(L/2) + t/2
    const int s    = id - pair * SLOTS;          // slot 0..47
    const int t    = (pair & (L_DIM / 2 - 1)) * 2;   // even row in [0, L)

    // Base channel residue: (8*s) % 3 == (2*s) % 3 (same for both rows)
    const int m = (2 * s) % 3;
    const bool is1 = (m == 1), is2 = (m == 2);

    // Flat element offset of (row t, slot s) for this pair's batch.
    const size_t base = ((size_t)(pair / (L_DIM / 2)) * L_DIM + t) * C_DIM + 8 * s;
    const float* p = in + base;

    uint32_t A[8], Bv[8], Cv[8], D[8];           // rows t-1, t, t+1, t+2
    ld8(Bv, p);
    ld8(Cv, p + C_DIM);
    if (t > 0) {
        ld8(A, p - C_DIM);
    } else {
        #pragma unroll
        for (int j = 0; j < 8; ++j) A[j] = 0u;
    }
    if (t + 2 < L_DIM) {
        ld8(D, p + 2 * C_DIM);
    } else {
        #pragma unroll
        for (int j = 0; j < 8; ++j) D[j] = 0u;
    }

    uint32_t o0[8], o1[8];
    route8(o0, A,  Bv, Cv, is1, is2);            // output row t
    route8(o1, Bv, Cv, D,  is1, is2);            // output row t+1

    float* q = out + base;
    st8(q,         o0);
    st8(q + C_DIM, o1);
}

extern "C" void kernel_launch(void* const* d_in, const int* in_sizes, int n_in,
                              void* d_out, int out_size) {
    const float* mem = (const float*)d_in[0];
    float* out = (float*)d_out;
    (void)in_sizes; (void)n_in; (void)out_size;

    const int total = B_DIM * (L_DIM / 2) * SLOTS;    // 1,572,864 threads
    const int grid  = total / THREADS;                // 6144 blocks
    ShiftLayer_66932770341347_kernel<<<grid, THREADS>>>(mem, out);
}

// round 17
// speedup vs baseline: 1.0136x; 1.0063x over previous
#include <cuda_runtime.h>
#include <cuda_bf16.h>
#include <cstdint>

// ShiftLayer: out[b,t,c] = in[b, t+off[c], c], off[c] = {0,-1,+1} for c%3 = {0,1,2},
// zero padding at sequence ends. B=8, L=8192, C=384, fp32.
//
// Champion paired-row 256-bit kernel (R12) with ONE change: loads use the
// NATIVE ld.global.L2::evict_last.v8.b32 modifier (legal only at 256-bit
// width on sm_103a - this encoding has never been run; R9's regressing
// variant used the createpolicy+cache_hint descriptor path instead).
// Rationale: harness steady state is bandwidth-floor-bound at ~201MB/replay
// (100.7MB read + 100.7MB write). The input fits the 126MB L2; pinning it
// with evict_last while the write-once output streams through the
// evict_first pool cuts steady-state DRAM traffic toward ~110-130MB.
//
// One thread produces TWO consecutive output rows (t, t+1) at one 8-channel
// slot: 4 independent LDG.256 (rows t-1..t+2), two routed STG.256 with
// L2::evict_first.

#define B_DIM 8
#define L_DIM 8192
#define C_DIM 384
#define SLOTS (C_DIM / 8)               // 48 float8 slots per row
#define THREADS 256

__device__ __forceinline__ void ld8(uint32_t* d, const float* p) {
    asm volatile("ld.global.L2::evict_last.v8.b32 {%0,%1,%2,%3,%4,%5,%6,%7}, [%8];"
                 : "=r"(d[0]), "=r"(d[1]), "=r"(d[2]), "=r"(d[3]),
                   "=r"(d[4]), "=r"(d[5]), "=r"(d[6]), "=r"(d[7])
                 : "l"(p));
}
__device__ __forceinline__ void st8(float* p, const uint32_t* v) {
    asm volatile("st.global.L2::evict_first.v8.b32 [%0], {%1,%2,%3,%4,%5,%6,%7,%8};"
                 :: "l"(p),
                    "r"(v[0]), "r"(v[1]), "r"(v[2]), "r"(v[3]),
                    "r"(v[4]), "r"(v[5]), "r"(v[6]), "r"(v[7])
                 : "memory");
}

// Component j has channel residue (m + j) % 3; residue 0 -> C, 1 -> P, 2 -> N.
__device__ __forceinline__ void route8(uint32_t* o, const uint32_t* P,
                                       const uint32_t* C, const uint32_t* N,
                                       bool is1, bool is2) {
    #pragma unroll
    for (int j = 0; j < 8; ++j) {
        const int jc = j % 3;
        if (jc == 0)      o[j] = is1 ? P[j] : (is2 ? N[j] : C[j]);
        else if (jc == 1) o[j] = is1 ? N[j] : (is2 ? C[j] : P[j]);
        else              o[j] = is1 ? C[j] : (is2 ? P[j] : N[j]);
    }
}

__global__ __launch_bounds__(THREADS, 4)
void ShiftLayer_66932770341347_kernel(const float* __restrict__ in,
                                      float* __restrict__ out) {
    const int id = blockIdx.x * THREADS + threadIdx.x;   // (row-pair, slot) index

    const int pair = id / SLOTS;                 // b*(L/2) + t/2
    const int s    = id - pair * SLOTS;          // slot 0..47
    const int t    = (pair & (L_DIM / 2 - 1)) * 2;   // even row in [0, L)

    // Base channel residue: (8*s) % 3 == (2*s) % 3 (same for both rows)
    const int m = (2 * s) % 3;
    const bool is1 = (m == 1), is2 = (m == 2);

    // Flat element offset of (row t, slot s) for this pair's batch.
    const size_t base = ((size_t)(pair / (L_DIM / 2)) * L_DIM + t) * C_DIM + 8 * s;
    const float* p = in + base;

    uint32_t A[8], Bv[8], Cv[8], D[8];           // rows t-1, t, t+1, t+2
    ld8(Bv, p);
    ld8(Cv, p + C_DIM);
    if (t > 0) {
        ld8(A, p - C_DIM);
    } else {
        #pragma unroll
        for (int j = 0; j < 8; ++j) A[j] = 0u;
    }
    if (t + 2 < L_DIM) {
        ld8(D, p + 2 * C_DIM);
    } else {
        #pragma unroll
        for (int j = 0; j < 8; ++j) D[j] = 0u;
    }

    uint32_t o0[8], o1[8];
    route8(o0, A,  Bv, Cv, is1, is2);            // output row t
    route8(o1, Bv, Cv, D,  is1, is2);            // output row t+1

    float* q = out + base;
    st8(q,         o0);
    st8(q + C_DIM, o1);
}

extern "C" void kernel_launch(void* const* d_in, const int* in_sizes, int n_in,
                              void* d_out, int out_size) {
    const float* mem = (const float*)d_in[0];
    float* out = (float*)d_out;
    (void)in_sizes; (void)n_in; (void)out_size;

    const int total = B_DIM * (L_DIM / 2) * SLOTS;    // 1,572,864 threads
    const int grid  = total / THREADS;                // 6144 blocks
    ShiftLayer_66932770341347_kernel<<<grid, THREADS>>>(mem, out);
}